// round 4
// baseline (speedup 1.0000x reference)
#include <cuda_runtime.h>

// GARCH-LSTM fused cell. B rows, H=16.
// Thread owns 2 h-values (g = lane&7, h = 2g,2g+1). BATCH=8 rows' loads
// front-batched (24 LDGs in flight/thread-group), streaming hints.
// sigmoid(x) = 0.5 + 0.5*tanh(x/2), 0.5 pre-folded into coefficients.

__device__ __forceinline__ float fast_tanh(float x) {
    float r;
    asm("tanh.approx.f32 %0, %1;" : "=f"(r) : "f"(x));
    return r;
}

#define BATCH 8

__global__ void __launch_bounds__(128)
garch_lstm_kernel(
    const float* __restrict__ eps,
    const float* __restrict__ sigma2,
    const float2* __restrict__ c_prev2,
    const float* __restrict__ Wf_w, const float* __restrict__ Wf_b,
    const float* __restrict__ Uf_w, const float* __restrict__ Uf_b,
    const float* __restrict__ Wi_w, const float* __restrict__ Wi_b,
    const float* __restrict__ Ui_w, const float* __restrict__ Ui_b,
    const float* __restrict__ Wc_w, const float* __restrict__ Wc_b,
    const float* __restrict__ Uc_w, const float* __restrict__ Uc_b,
    const float* __restrict__ b_f, const float* __restrict__ b_i,
    const float* __restrict__ b_c,
    const float* __restrict__ w,
    const float* __restrict__ garch_w,
    const float* __restrict__ garch_b,
    float* __restrict__ out, int B)
{
    const int g  = threadIdx.x & 7;   // h-pair: handles h = 2g, 2g+1
    const int h0 = g * 2;

    // Loop-invariant coefficients (18 regs), pre-scaled by 0.5.
    float Af[2], Bf[2], Cf[2], Ai[2], Bi[2], Ci[2], Ac[2], Bc[2], Cc[2];
    const float bfv = __ldg(b_f), biv = __ldg(b_i), bcv = __ldg(b_c);
    #pragma unroll
    for (int j = 0; j < 2; j++) {
        const int h = h0 + j;
        Af[j] = 0.5f * __ldg(Wf_w + h);
        Bf[j] = 0.5f * __ldg(Uf_w + h);
        Cf[j] = 0.5f * (__ldg(Wf_b + h) + __ldg(Uf_b + h) + bfv);
        Ai[j] = 0.5f * __ldg(Wi_w + h);
        Bi[j] = 0.5f * __ldg(Ui_w + h);
        Ci[j] = 0.5f * (__ldg(Wi_b + h) + __ldg(Ui_b + h) + biv);
        Ac[j] = 0.5f * __ldg(Wc_w + h);
        Bc[j] = 0.5f * __ldg(Uc_w + h);
        Cc[j] = 0.5f * (__ldg(Wc_b + h) + __ldg(Uc_b + h) + bcv);
    }

    const float gw1 = __ldg(garch_w + 1);
    const float gw2 = __ldg(garch_w + 2);
    const float gw3 = __ldg(garch_w + 3);
    const float gc  = __ldg(garch_w + 0) + __ldg(garch_b);
    const float wv  = __ldg(w) * (1.0f / 16.0f);

    float*  __restrict__ out_sig = out;                  // sigma2_t : B
    float2* __restrict__ out_c2  = (float2*)(out + B);   // c_t      : B*16

    const int stride = (gridDim.x * blockDim.x) >> 3;    // rows per sweep
    int r = (blockIdx.x * blockDim.x + threadIdx.x) >> 3;

    // Fast path: BATCH rows per iteration, all loads front-batched.
    for (; r + (BATCH - 1) * stride < B; r += BATCH * stride) {
        float  e[BATCH], s[BATCH];
        float2 cp[BATCH];
        #pragma unroll
        for (int k = 0; k < BATCH; k++) {
            const int rk = r + k * stride;
            e[k]  = __ldcs(eps + rk);
            s[k]  = __ldcs(sigma2 + rk);
            cp[k] = __ldcs(c_prev2 + (size_t)rk * 8 + g);
        }

        #pragma unroll
        for (int k = 0; k < BATCH; k++) {
            const int rk = r + k * stride;
            const float cpv[2] = {cp[k].x, cp[k].y};
            float c[2];
            float thsum = 0.0f;
            #pragma unroll
            for (int j = 0; j < 2; j++) {
                const float f_t   = fmaf(0.5f, fast_tanh(fmaf(e[k], Af[j], fmaf(s[k], Bf[j], Cf[j]))), 0.5f);
                const float i_t   = fmaf(0.5f, fast_tanh(fmaf(e[k], Ai[j], fmaf(s[k], Bi[j], Ci[j]))), 0.5f);
                const float c_hat = fmaf(0.5f, fast_tanh(fmaf(e[k], Ac[j], fmaf(s[k], Bc[j], Cc[j]))), 0.5f);
                c[j] = fmaf(f_t, cpv[j], i_t * c_hat);
                thsum += fast_tanh(c[j]);
            }

            __stcs(out_c2 + (size_t)rk * 8 + g, make_float2(c[0], c[1]));

            thsum += __shfl_xor_sync(0xffffffffu, thsum, 1);
            thsum += __shfl_xor_sync(0xffffffffu, thsum, 2);
            thsum += __shfl_xor_sync(0xffffffffu, thsum, 4);

            if (g == 0) {
                const float e2 = e[k] * e[k];
                const float ga = (e[k] < 0.0f) ? gw2 : 0.0f;
                float o = fmaf(gw1 + ga, e2, fmaf(gw3, s[k], gc));
                __stcs(out_sig + rk, o * fmaf(wv, thsum, 1.0f));
            }
        }
    }

    // Tail (not taken for B = 2M with this grid).
    for (; r < B; r += stride) {
        const float  e  = __ldcs(eps + r);
        const float  s  = __ldcs(sigma2 + r);
        const float2 cp = __ldcs(c_prev2 + (size_t)r * 8 + g);
        const float cpv[2] = {cp.x, cp.y};
        float c[2];
        float thsum = 0.0f;
        #pragma unroll
        for (int j = 0; j < 2; j++) {
            const float f_t   = fmaf(0.5f, fast_tanh(fmaf(e, Af[j], fmaf(s, Bf[j], Cf[j]))), 0.5f);
            const float i_t   = fmaf(0.5f, fast_tanh(fmaf(e, Ai[j], fmaf(s, Bi[j], Ci[j]))), 0.5f);
            const float c_hat = fmaf(0.5f, fast_tanh(fmaf(e, Ac[j], fmaf(s, Bc[j], Cc[j]))), 0.5f);
            c[j] = fmaf(f_t, cpv[j], i_t * c_hat);
            thsum += fast_tanh(c[j]);
        }
        __stcs(out_c2 + (size_t)r * 8 + g, make_float2(c[0], c[1]));
        thsum += __shfl_xor_sync(0xffffffffu, thsum, 1);
        thsum += __shfl_xor_sync(0xffffffffu, thsum, 2);
        thsum += __shfl_xor_sync(0xffffffffu, thsum, 4);
        if (g == 0) {
            const float e2 = e * e;
            const float ga = (e < 0.0f) ? gw2 : 0.0f;
            float o = fmaf(gw1 + ga, e2, fmaf(gw3, s, gc));
            __stcs(out_sig + r, o * fmaf(wv, thsum, 1.0f));
        }
    }
}

extern "C" void kernel_launch(void* const* d_in, const int* in_sizes, int n_in,
                              void* d_out, int out_size) {
    const float* p[21];
    if (n_in >= 21 && in_sizes[7] == 1) {
        // reference-signature order
        const int map[21] = {0, 1, 2,
                             3, 4, 5, 6,      // Wf_w Wf_b Uf_w Uf_b
                             8, 9, 10, 11,    // Wi_w Wi_b Ui_w Ui_b
                             13, 14, 15, 16,  // Wc_w Wc_b Uc_w Uc_b
                             7, 12, 17,       // b_f b_i b_c
                             18, 19, 20};     // w garch_w garch_b
        for (int i = 0; i < 21; i++) p[i] = (const float*)d_in[map[i]];
    } else {
        // setup_inputs dict order
        for (int i = 0; i < 21; i++) p[i] = (const float*)d_in[i];
    }

    const int B = in_sizes[0];
    float* out = (float*)d_out;

    // 2048 blocks x 128 threads = 262144 threads -> 32768 rows/sweep
    // -> 64 sweeps -> 8 outer BATCH=8 iterations for B = 2M. Exact.
    garch_lstm_kernel<<<2048, 128>>>(
        p[0], p[1], (const float2*)p[2],
        p[3], p[4], p[5], p[6],
        p[7], p[8], p[9], p[10],
        p[11], p[12], p[13], p[14],
        p[15], p[16], p[17],
        p[18], p[19], p[20],
        out, B);
}

// round 5
// speedup vs baseline: 1.1628x; 1.1628x over previous
#include <cuda_runtime.h>

// GARCH-LSTM fused cell. B rows, H=16.
// R3-proven layout: thread owns 4 h-values (g=lane&3), float4 c_prev/c_t,
// 2-level shfl. Deepened pipeline: BATCH=8 rows' loads front-batched
// (~192B in flight per thread), streaming cache hints.
// sigmoid(x) = 0.5 + 0.5*tanh(x/2), 0.5 pre-folded into coefficients.

__device__ __forceinline__ float fast_tanh(float x) {
    float r;
    asm("tanh.approx.f32 %0, %1;" : "=f"(r) : "f"(x));
    return r;
}

#define BATCH 8

__global__ void __launch_bounds__(128)
garch_lstm_kernel(
    const float* __restrict__ eps,
    const float* __restrict__ sigma2,
    const float4* __restrict__ c_prev4,
    const float* __restrict__ Wf_w, const float* __restrict__ Wf_b,
    const float* __restrict__ Uf_w, const float* __restrict__ Uf_b,
    const float* __restrict__ Wi_w, const float* __restrict__ Wi_b,
    const float* __restrict__ Ui_w, const float* __restrict__ Ui_b,
    const float* __restrict__ Wc_w, const float* __restrict__ Wc_b,
    const float* __restrict__ Uc_w, const float* __restrict__ Uc_b,
    const float* __restrict__ b_f, const float* __restrict__ b_i,
    const float* __restrict__ b_c,
    const float* __restrict__ w,
    const float* __restrict__ garch_w,
    const float* __restrict__ garch_b,
    float* __restrict__ out, int B)
{
    const int g  = threadIdx.x & 3;   // h-group: handles h = 4g..4g+3
    const int h0 = g * 4;

    // Loop-invariant coefficients (36 regs), pre-scaled by 0.5.
    float Af[4], Bf[4], Cf[4], Ai[4], Bi[4], Ci[4], Ac[4], Bc[4], Cc[4];
    const float bfv = __ldg(b_f), biv = __ldg(b_i), bcv = __ldg(b_c);
    #pragma unroll
    for (int j = 0; j < 4; j++) {
        const int h = h0 + j;
        Af[j] = 0.5f * __ldg(Wf_w + h);
        Bf[j] = 0.5f * __ldg(Uf_w + h);
        Cf[j] = 0.5f * (__ldg(Wf_b + h) + __ldg(Uf_b + h) + bfv);
        Ai[j] = 0.5f * __ldg(Wi_w + h);
        Bi[j] = 0.5f * __ldg(Ui_w + h);
        Ci[j] = 0.5f * (__ldg(Wi_b + h) + __ldg(Ui_b + h) + biv);
        Ac[j] = 0.5f * __ldg(Wc_w + h);
        Bc[j] = 0.5f * __ldg(Uc_w + h);
        Cc[j] = 0.5f * (__ldg(Wc_b + h) + __ldg(Uc_b + h) + bcv);
    }

    const float gw1 = __ldg(garch_w + 1);
    const float gw2 = __ldg(garch_w + 2);
    const float gw3 = __ldg(garch_w + 3);
    const float gc  = __ldg(garch_w + 0) + __ldg(garch_b);
    const float wv  = __ldg(w) * (1.0f / 16.0f);

    float*  __restrict__ out_sig = out;                  // sigma2_t : B
    float4* __restrict__ out_c4  = (float4*)(out + B);   // c_t      : B*16

    const int stride = (gridDim.x * blockDim.x) >> 2;    // rows per sweep
    int r = (blockIdx.x * blockDim.x + threadIdx.x) >> 2;

    // Fast path: BATCH rows per iteration, all loads front-batched.
    for (; r + (BATCH - 1) * stride < B; r += BATCH * stride) {
        float  e[BATCH], s[BATCH];
        float4 cp[BATCH];
        #pragma unroll
        for (int k = 0; k < BATCH; k++) {
            const int rk = r + k * stride;
            e[k]  = __ldcs(eps + rk);
            s[k]  = __ldcs(sigma2 + rk);
            cp[k] = __ldcs(c_prev4 + (size_t)rk * 4 + g);
        }

        #pragma unroll
        for (int k = 0; k < BATCH; k++) {
            const int rk = r + k * stride;
            const float cpv[4] = {cp[k].x, cp[k].y, cp[k].z, cp[k].w};
            float c[4];
            float thsum = 0.0f;
            #pragma unroll
            for (int j = 0; j < 4; j++) {
                const float f_t   = fmaf(0.5f, fast_tanh(fmaf(e[k], Af[j], fmaf(s[k], Bf[j], Cf[j]))), 0.5f);
                const float i_t   = fmaf(0.5f, fast_tanh(fmaf(e[k], Ai[j], fmaf(s[k], Bi[j], Ci[j]))), 0.5f);
                const float c_hat = fmaf(0.5f, fast_tanh(fmaf(e[k], Ac[j], fmaf(s[k], Bc[j], Cc[j]))), 0.5f);
                c[j] = fmaf(f_t, cpv[j], i_t * c_hat);
                thsum += fast_tanh(c[j]);
            }

            __stcs(out_c4 + (size_t)rk * 4 + g, make_float4(c[0], c[1], c[2], c[3]));

            thsum += __shfl_xor_sync(0xffffffffu, thsum, 1);
            thsum += __shfl_xor_sync(0xffffffffu, thsum, 2);

            if (g == 0) {
                const float e2 = e[k] * e[k];
                const float ga = (e[k] < 0.0f) ? gw2 : 0.0f;
                float o = fmaf(gw1 + ga, e2, fmaf(gw3, s[k], gc));
                __stcs(out_sig + rk, o * fmaf(wv, thsum, 1.0f));
            }
        }
    }

    // Tail (not taken for B = 2M with this grid; kept for generality).
    for (; r < B; r += stride) {
        const float  e  = __ldcs(eps + r);
        const float  s  = __ldcs(sigma2 + r);
        const float4 cp = __ldcs(c_prev4 + (size_t)r * 4 + g);
        const float cpv[4] = {cp.x, cp.y, cp.z, cp.w};
        float c[4];
        float thsum = 0.0f;
        #pragma unroll
        for (int j = 0; j < 4; j++) {
            const float f_t   = fmaf(0.5f, fast_tanh(fmaf(e, Af[j], fmaf(s, Bf[j], Cf[j]))), 0.5f);
            const float i_t   = fmaf(0.5f, fast_tanh(fmaf(e, Ai[j], fmaf(s, Bi[j], Ci[j]))), 0.5f);
            const float c_hat = fmaf(0.5f, fast_tanh(fmaf(e, Ac[j], fmaf(s, Bc[j], Cc[j]))), 0.5f);
            c[j] = fmaf(f_t, cpv[j], i_t * c_hat);
            thsum += fast_tanh(c[j]);
        }
        __stcs(out_c4 + (size_t)r * 4 + g, make_float4(c[0], c[1], c[2], c[3]));
        thsum += __shfl_xor_sync(0xffffffffu, thsum, 1);
        thsum += __shfl_xor_sync(0xffffffffu, thsum, 2);
        if (g == 0) {
            const float e2 = e * e;
            const float ga = (e < 0.0f) ? gw2 : 0.0f;
            float o = fmaf(gw1 + ga, e2, fmaf(gw3, s, gc));
            __stcs(out_sig + r, o * fmaf(wv, thsum, 1.0f));
        }
    }
}

extern "C" void kernel_launch(void* const* d_in, const int* in_sizes, int n_in,
                              void* d_out, int out_size) {
    const float* p[21];
    if (n_in >= 21 && in_sizes[7] == 1) {
        // reference-signature order
        const int map[21] = {0, 1, 2,
                             3, 4, 5, 6,      // Wf_w Wf_b Uf_w Uf_b
                             8, 9, 10, 11,    // Wi_w Wi_b Ui_w Ui_b
                             13, 14, 15, 16,  // Wc_w Wc_b Uc_w Uc_b
                             7, 12, 17,       // b_f b_i b_c
                             18, 19, 20};     // w garch_w garch_b
        for (int i = 0; i < 21; i++) p[i] = (const float*)d_in[map[i]];
    } else {
        // setup_inputs dict order
        for (int i = 0; i < 21; i++) p[i] = (const float*)d_in[i];
    }

    const int B = in_sizes[0];
    float* out = (float*)d_out;

    // 2048 blocks x 128 threads -> 65536 rows/sweep -> 32 sweeps
    // -> exactly 4 outer BATCH=8 iterations for B = 2M.
    garch_lstm_kernel<<<2048, 128>>>(
        p[0], p[1], (const float4*)p[2],
        p[3], p[4], p[5], p[6],
        p[7], p[8], p[9], p[10],
        p[11], p[12], p[13], p[14],
        p[15], p[16], p[17],
        p[18], p[19], p[20],
        out, B);
}

// round 7
// speedup vs baseline: 1.2275x; 1.0557x over previous
#include <cuda_runtime.h>
#include <cuda_fp16.h>

// GARCH-LSTM fused cell. B rows, H=16.
// Warp = 8 slots x 4 g-lanes; slot owns 32 contiguous rows (4 iters x 8).
// e/s loaded as float4 pairs, c_prev/c_t as float4, sigma2_t stored as float4
// pairs. Gate tanh + mean-tanh computed via tanh.approx.f16x2 (args in f32).
// sigmoid(x) = 0.5 + 0.5*tanh(x/2), 0.5 pre-folded into coefficients.

__device__ __forceinline__ half2 h2_tanh_approx(half2 x) {
    unsigned int u = *reinterpret_cast<unsigned int*>(&x);
    asm("tanh.approx.f16x2 %0, %1;" : "=r"(u) : "r"(u));
    return *reinterpret_cast<half2*>(&u);
}

__global__ void __launch_bounds__(128)
garch_lstm_kernel(
    const float* __restrict__ eps,
    const float* __restrict__ sigma2,
    const float4* __restrict__ c_prev4,
    const float* __restrict__ Wf_w, const float* __restrict__ Wf_b,
    const float* __restrict__ Uf_w, const float* __restrict__ Uf_b,
    const float* __restrict__ Wi_w, const float* __restrict__ Wi_b,
    const float* __restrict__ Ui_w, const float* __restrict__ Ui_b,
    const float* __restrict__ Wc_w, const float* __restrict__ Wc_b,
    const float* __restrict__ Uc_w, const float* __restrict__ Uc_b,
    const float* __restrict__ b_f, const float* __restrict__ b_i,
    const float* __restrict__ b_c,
    const float* __restrict__ w,
    const float* __restrict__ garch_w,
    const float* __restrict__ garch_b,
    float* __restrict__ out, int B)
{
    const int lane = threadIdx.x & 31;
    const int g    = lane & 3;        // h-group: h = 4g..4g+3
    const int slot = lane >> 2;       // 8 slots per warp
    const int h0   = g * 4;

    // Loop-invariant coefficients (36 regs), pre-scaled by 0.5.
    float Af[4], Bf[4], Cf[4], Ai[4], Bi[4], Ci[4], Ac[4], Bc[4], Cc[4];
    const float bfv = __ldg(b_f), biv = __ldg(b_i), bcv = __ldg(b_c);
    #pragma unroll
    for (int j = 0; j < 4; j++) {
        const int h = h0 + j;
        Af[j] = 0.5f * __ldg(Wf_w + h);
        Bf[j] = 0.5f * __ldg(Uf_w + h);
        Cf[j] = 0.5f * (__ldg(Wf_b + h) + __ldg(Uf_b + h) + bfv);
        Ai[j] = 0.5f * __ldg(Wi_w + h);
        Bi[j] = 0.5f * __ldg(Ui_w + h);
        Ci[j] = 0.5f * (__ldg(Wi_b + h) + __ldg(Ui_b + h) + biv);
        Ac[j] = 0.5f * __ldg(Wc_w + h);
        Bc[j] = 0.5f * __ldg(Uc_w + h);
        Cc[j] = 0.5f * (__ldg(Wc_b + h) + __ldg(Uc_b + h) + bcv);
    }

    const float gw1 = __ldg(garch_w + 1);
    const float gw2 = __ldg(garch_w + 2);
    const float gw3 = __ldg(garch_w + 3);
    const float gc  = __ldg(garch_w + 0) + __ldg(garch_b);
    const float wv  = __ldg(w) * (1.0f / 16.0f);

    float*  __restrict__ out_sig = out;                  // sigma2_t : B
    float4* __restrict__ out_c4  = (float4*)(out + B);   // c_t      : B*16

    const int nwarps = (gridDim.x * blockDim.x) >> 5;
    const int warpId = (blockIdx.x * blockDim.x + threadIdx.x) >> 5;
    const long long chunk_stride = (long long)nwarps * 256;

    for (long long chunk = (long long)warpId * 256; chunk < B; chunk += chunk_stride) {
        const long long tbase = chunk + slot * 32;       // 32 contiguous rows

        #pragma unroll 1
        for (int it = 0; it < 4; it++) {
            const long long r0 = tbase + it * 8;
            if (r0 + 8 > B) break;   // not taken for B = 2M

            // ---- front-batched loads (12 LDG) ----
            const float4 ea = __ldcs((const float4*)(eps + r0));
            const float4 eb = __ldcs((const float4*)(eps + r0 + 4));
            const float4 sa = __ldcs((const float4*)(sigma2 + r0));
            const float4 sb = __ldcs((const float4*)(sigma2 + r0 + 4));
            float4 cp[8];
            #pragma unroll
            for (int k = 0; k < 8; k++)
                cp[k] = __ldcs(c_prev4 + (r0 + k) * 4 + g);

            const float ev[8] = {ea.x, ea.y, ea.z, ea.w, eb.x, eb.y, eb.z, eb.w};
            const float sv[8] = {sa.x, sa.y, sa.z, sa.w, sb.x, sb.y, sb.z, sb.w};

            float sig[8];

            #pragma unroll
            for (int k = 0; k < 8; k++) {
                const float e = ev[k], s = sv[k];
                const float cpv[4] = {cp[k].x, cp[k].y, cp[k].z, cp[k].w};

                // gate tanh via f16x2 (args computed in f32)
                const half2 tf01 = h2_tanh_approx(__floats2half2_rn(
                    fmaf(e, Af[0], fmaf(s, Bf[0], Cf[0])),
                    fmaf(e, Af[1], fmaf(s, Bf[1], Cf[1]))));
                const half2 tf23 = h2_tanh_approx(__floats2half2_rn(
                    fmaf(e, Af[2], fmaf(s, Bf[2], Cf[2])),
                    fmaf(e, Af[3], fmaf(s, Bf[3], Cf[3]))));
                const half2 ti01 = h2_tanh_approx(__floats2half2_rn(
                    fmaf(e, Ai[0], fmaf(s, Bi[0], Ci[0])),
                    fmaf(e, Ai[1], fmaf(s, Bi[1], Ci[1]))));
                const half2 ti23 = h2_tanh_approx(__floats2half2_rn(
                    fmaf(e, Ai[2], fmaf(s, Bi[2], Ci[2])),
                    fmaf(e, Ai[3], fmaf(s, Bi[3], Ci[3]))));
                const half2 tc01 = h2_tanh_approx(__floats2half2_rn(
                    fmaf(e, Ac[0], fmaf(s, Bc[0], Cc[0])),
                    fmaf(e, Ac[1], fmaf(s, Bc[1], Cc[1]))));
                const half2 tc23 = h2_tanh_approx(__floats2half2_rn(
                    fmaf(e, Ac[2], fmaf(s, Bc[2], Cc[2])),
                    fmaf(e, Ac[3], fmaf(s, Bc[3], Cc[3]))));

                const float tf[4] = {__low2float(tf01), __high2float(tf01),
                                     __low2float(tf23), __high2float(tf23)};
                const float ti[4] = {__low2float(ti01), __high2float(ti01),
                                     __low2float(ti23), __high2float(ti23)};
                const float tc[4] = {__low2float(tc01), __high2float(tc01),
                                     __low2float(tc23), __high2float(tc23)};

                float c[4];
                #pragma unroll
                for (int j = 0; j < 4; j++) {
                    const float f_t   = fmaf(0.5f, tf[j], 0.5f);
                    const float i_t   = fmaf(0.5f, ti[j], 0.5f);
                    const float c_hat = fmaf(0.5f, tc[j], 0.5f);
                    c[j] = fmaf(f_t, cpv[j], i_t * c_hat);
                }

                __stcs(out_c4 + (r0 + k) * 4 + g,
                       make_float4(c[0], c[1], c[2], c[3]));

                // mean tanh(c) via f16x2
                const half2 t01 = h2_tanh_approx(__floats2half2_rn(c[0], c[1]));
                const half2 t23 = h2_tanh_approx(__floats2half2_rn(c[2], c[3]));
                const half2 ts  = __hadd2(t01, t23);
                float thsum = __low2float(ts) + __high2float(ts);

                thsum += __shfl_xor_sync(0xffffffffu, thsum, 1);
                thsum += __shfl_xor_sync(0xffffffffu, thsum, 2);

                const float e2 = e * e;
                const float ga = (e < 0.0f) ? gw2 : 0.0f;
                const float o  = fmaf(gw1 + ga, e2, fmaf(gw3, s, gc));
                sig[k] = o * fmaf(wv, thsum, 1.0f);
            }

            if (g == 0) {
                __stcs((float4*)(out_sig + r0),
                       make_float4(sig[0], sig[1], sig[2], sig[3]));
                __stcs((float4*)(out_sig + r0 + 4),
                       make_float4(sig[4], sig[5], sig[6], sig[7]));
            }
        }
    }
}

extern "C" void kernel_launch(void* const* d_in, const int* in_sizes, int n_in,
                              void* d_out, int out_size) {
    const float* p[21];
    if (n_in >= 21 && in_sizes[7] == 1) {
        // reference-signature order
        const int map[21] = {0, 1, 2,
                             3, 4, 5, 6,      // Wf_w Wf_b Uf_w Uf_b
                             8, 9, 10, 11,    // Wi_w Wi_b Ui_w Ui_b
                             13, 14, 15, 16,  // Wc_w Wc_b Uc_w Uc_b
                             7, 12, 17,       // b_f b_i b_c
                             18, 19, 20};     // w garch_w garch_b
        for (int i = 0; i < 21; i++) p[i] = (const float*)d_in[map[i]];
    } else {
        // setup_inputs dict order
        for (int i = 0; i < 21; i++) p[i] = (const float*)d_in[i];
    }

    const int B = in_sizes[0];
    float* out = (float*)d_out;

    // 2048 blocks x 128 threads = 8192 warps x 256 rows = 2,097,152 = B exact.
    garch_lstm_kernel<<<2048, 128>>>(
        p[0], p[1], (const float4*)p[2],
        p[3], p[4], p[5], p[6],
        p[7], p[8], p[9], p[10],
        p[11], p[12], p[13], p[14],
        p[15], p[16], p[17],
        p[18], p[19], p[20],
        out, B);
}

// round 8
// speedup vs baseline: 1.2298x; 1.0018x over previous
#include <cuda_runtime.h>
#include <cuda_fp16.h>

// GARCH-LSTM fused cell. B rows, H=16.
// Warp = 8 slots x 4 g-lanes; slot owns 32 contiguous rows (4 iters x 8).
// Gate args via packed fma.rn.f32x2 (FFMA2), gate tanh via tanh.approx.f16x2,
// gate scaling + i*chat product in half2, c_t combine in f32.
// sigmoid(x) = 0.5 + 0.5*tanh(x/2), 0.5 pre-folded into coefficients.

typedef unsigned long long u64;

__device__ __forceinline__ u64 pk2(float lo, float hi) {
    u64 r; asm("mov.b64 %0, {%1, %2};" : "=l"(r) : "f"(lo), "f"(hi)); return r;
}
__device__ __forceinline__ float2 up2(u64 v) {
    float2 f; asm("mov.b64 {%0, %1}, %2;" : "=f"(f.x), "=f"(f.y) : "l"(v)); return f;
}
__device__ __forceinline__ u64 ffma2(u64 a, u64 b, u64 c) {
    u64 d; asm("fma.rn.f32x2 %0, %1, %2, %3;" : "=l"(d) : "l"(a), "l"(b), "l"(c)); return d;
}
__device__ __forceinline__ half2 h2_tanh_approx(half2 x) {
    unsigned int u = *reinterpret_cast<unsigned int*>(&x);
    unsigned int r;
    asm("tanh.approx.f16x2 %0, %1;" : "=r"(r) : "r"(u));
    return *reinterpret_cast<half2*>(&r);
}
__device__ __forceinline__ half2 h2_from_u64(u64 v) {
    float2 q = up2(v);
    return __floats2half2_rn(q.x, q.y);
}

__global__ void __launch_bounds__(128)
garch_lstm_kernel(
    const float* __restrict__ eps,
    const float* __restrict__ sigma2,
    const float4* __restrict__ c_prev4,
    const float* __restrict__ Wf_w, const float* __restrict__ Wf_b,
    const float* __restrict__ Uf_w, const float* __restrict__ Uf_b,
    const float* __restrict__ Wi_w, const float* __restrict__ Wi_b,
    const float* __restrict__ Ui_w, const float* __restrict__ Ui_b,
    const float* __restrict__ Wc_w, const float* __restrict__ Wc_b,
    const float* __restrict__ Uc_w, const float* __restrict__ Uc_b,
    const float* __restrict__ b_f, const float* __restrict__ b_i,
    const float* __restrict__ b_c,
    const float* __restrict__ w,
    const float* __restrict__ garch_w,
    const float* __restrict__ garch_b,
    float* __restrict__ out, int B)
{
    const int lane = threadIdx.x & 31;
    const int g    = lane & 3;        // h-group: h = 4g..4g+3
    const int slot = lane >> 2;       // 8 slots per warp
    const int h0   = g * 4;

    // Packed loop-invariant coefficients (18 u64 = 36 f32), pre-scaled by 0.5.
    const float bfv = __ldg(b_f), biv = __ldg(b_i), bcv = __ldg(b_c);
    float A[3][4], Bb[3][4], C[3][4];
    #pragma unroll
    for (int j = 0; j < 4; j++) {
        const int h = h0 + j;
        A[0][j]  = 0.5f * __ldg(Wf_w + h);
        Bb[0][j] = 0.5f * __ldg(Uf_w + h);
        C[0][j]  = 0.5f * (__ldg(Wf_b + h) + __ldg(Uf_b + h) + bfv);
        A[1][j]  = 0.5f * __ldg(Wi_w + h);
        Bb[1][j] = 0.5f * __ldg(Ui_w + h);
        C[1][j]  = 0.5f * (__ldg(Wi_b + h) + __ldg(Ui_b + h) + biv);
        A[2][j]  = 0.5f * __ldg(Wc_w + h);
        Bb[2][j] = 0.5f * __ldg(Uc_w + h);
        C[2][j]  = 0.5f * (__ldg(Wc_b + h) + __ldg(Uc_b + h) + bcv);
    }
    u64 Ap[3][2], Bp[3][2], Cp[3][2];
    #pragma unroll
    for (int q = 0; q < 3; q++) {
        Ap[q][0] = pk2(A[q][0],  A[q][1]);  Ap[q][1] = pk2(A[q][2],  A[q][3]);
        Bp[q][0] = pk2(Bb[q][0], Bb[q][1]); Bp[q][1] = pk2(Bb[q][2], Bb[q][3]);
        Cp[q][0] = pk2(C[q][0],  C[q][1]);  Cp[q][1] = pk2(C[q][2],  C[q][3]);
    }

    const float gw1 = __ldg(garch_w + 1);
    const float gw2 = __ldg(garch_w + 2);
    const float gw3 = __ldg(garch_w + 3);
    const float gc  = __ldg(garch_w + 0) + __ldg(garch_b);
    const float wv  = __ldg(w) * (1.0f / 16.0f);
    const half2 H05 = __floats2half2_rn(0.5f, 0.5f);

    float*  __restrict__ out_sig = out;                  // sigma2_t : B
    float4* __restrict__ out_c4  = (float4*)(out + B);   // c_t      : B*16

    const int nwarps = (gridDim.x * blockDim.x) >> 5;
    const int warpId = (blockIdx.x * blockDim.x + threadIdx.x) >> 5;
    const long long chunk_stride = (long long)nwarps * 256;

    for (long long chunk = (long long)warpId * 256; chunk < B; chunk += chunk_stride) {
        const long long tbase = chunk + slot * 32;       // 32 contiguous rows

        #pragma unroll 1
        for (int it = 0; it < 4; it++) {
            const long long r0 = tbase + it * 8;
            if (r0 + 8 > B) break;   // not taken for B = 2M

            // ---- front-batched loads (12 LDG.128) ----
            const float4 ea = __ldcs((const float4*)(eps + r0));
            const float4 eb = __ldcs((const float4*)(eps + r0 + 4));
            const float4 sa = __ldcs((const float4*)(sigma2 + r0));
            const float4 sb = __ldcs((const float4*)(sigma2 + r0 + 4));
            float4 cp[8];
            #pragma unroll
            for (int k = 0; k < 8; k++)
                cp[k] = __ldcs(c_prev4 + (r0 + k) * 4 + g);

            const float ev[8] = {ea.x, ea.y, ea.z, ea.w, eb.x, eb.y, eb.z, eb.w};
            const float sv[8] = {sa.x, sa.y, sa.z, sa.w, sb.x, sb.y, sb.z, sb.w};

            float sig[8];

            #pragma unroll
            for (int k = 0; k < 8; k++) {
                const float e = ev[k], s = sv[k];
                const u64 ee = pk2(e, e);
                const u64 ss = pk2(s, s);

                // gate args: 12 FFMA2 (= 24 scalar FMA)
                const u64 af0 = ffma2(ee, Ap[0][0], ffma2(ss, Bp[0][0], Cp[0][0]));
                const u64 af1 = ffma2(ee, Ap[0][1], ffma2(ss, Bp[0][1], Cp[0][1]));
                const u64 ai0 = ffma2(ee, Ap[1][0], ffma2(ss, Bp[1][0], Cp[1][0]));
                const u64 ai1 = ffma2(ee, Ap[1][1], ffma2(ss, Bp[1][1], Cp[1][1]));
                const u64 ac0 = ffma2(ee, Ap[2][0], ffma2(ss, Bp[2][0], Cp[2][0]));
                const u64 ac1 = ffma2(ee, Ap[2][1], ffma2(ss, Bp[2][1], Cp[2][1]));

                // tanh in f16x2 (6 MUFU), scale + product in half2
                const half2 f01 = __hfma2(h2_tanh_approx(h2_from_u64(af0)), H05, H05);
                const half2 f23 = __hfma2(h2_tanh_approx(h2_from_u64(af1)), H05, H05);
                const half2 i01 = __hfma2(h2_tanh_approx(h2_from_u64(ai0)), H05, H05);
                const half2 i23 = __hfma2(h2_tanh_approx(h2_from_u64(ai1)), H05, H05);
                const half2 c01 = __hfma2(h2_tanh_approx(h2_from_u64(ac0)), H05, H05);
                const half2 c23 = __hfma2(h2_tanh_approx(h2_from_u64(ac1)), H05, H05);
                const half2 p01 = __hmul2(i01, c01);
                const half2 p23 = __hmul2(i23, c23);

                const float2 f01f = __half22float2(f01);
                const float2 f23f = __half22float2(f23);
                const float2 p01f = __half22float2(p01);
                const float2 p23f = __half22float2(p23);

                float c[4];
                c[0] = fmaf(f01f.x, cp[k].x, p01f.x);
                c[1] = fmaf(f01f.y, cp[k].y, p01f.y);
                c[2] = fmaf(f23f.x, cp[k].z, p23f.x);
                c[3] = fmaf(f23f.y, cp[k].w, p23f.y);

                __stcs(out_c4 + (r0 + k) * 4 + g,
                       make_float4(c[0], c[1], c[2], c[3]));

                // mean tanh(c) via f16x2
                const half2 t01 = h2_tanh_approx(__floats2half2_rn(c[0], c[1]));
                const half2 t23 = h2_tanh_approx(__floats2half2_rn(c[2], c[3]));
                const half2 ts  = __hadd2(t01, t23);
                float thsum = __low2float(ts) + __high2float(ts);

                thsum += __shfl_xor_sync(0xffffffffu, thsum, 1);
                thsum += __shfl_xor_sync(0xffffffffu, thsum, 2);

                const float e2 = e * e;
                const float ga = (e < 0.0f) ? gw2 : 0.0f;
                const float o  = fmaf(gw1 + ga, e2, fmaf(gw3, s, gc));
                sig[k] = o * fmaf(wv, thsum, 1.0f);
            }

            if (g == 0) {
                __stcs((float4*)(out_sig + r0),
                       make_float4(sig[0], sig[1], sig[2], sig[3]));
                __stcs((float4*)(out_sig + r0 + 4),
                       make_float4(sig[4], sig[5], sig[6], sig[7]));
            }
        }
    }
}

extern "C" void kernel_launch(void* const* d_in, const int* in_sizes, int n_in,
                              void* d_out, int out_size) {
    const float* p[21];
    if (n_in >= 21 && in_sizes[7] == 1) {
        // reference-signature order
        const int map[21] = {0, 1, 2,
                             3, 4, 5, 6,      // Wf_w Wf_b Uf_w Uf_b
                             8, 9, 10, 11,    // Wi_w Wi_b Ui_w Ui_b
                             13, 14, 15, 16,  // Wc_w Wc_b Uc_w Uc_b
                             7, 12, 17,       // b_f b_i b_c
                             18, 19, 20};     // w garch_w garch_b
        for (int i = 0; i < 21; i++) p[i] = (const float*)d_in[map[i]];
    } else {
        // setup_inputs dict order
        for (int i = 0; i < 21; i++) p[i] = (const float*)d_in[i];
    }

    const int B = in_sizes[0];
    float* out = (float*)d_out;

    // 2048 blocks x 128 threads = 8192 warps x 256 rows = 2,097,152 = B exact.
    garch_lstm_kernel<<<2048, 128>>>(
        p[0], p[1], (const float4*)p[2],
        p[3], p[4], p[5], p[6],
        p[7], p[8], p[9], p[10],
        p[11], p[12], p[13], p[14],
        p[15], p[16], p[17],
        p[18], p[19], p[20],
        out, B);
}